// round 7
// baseline (speedup 1.0000x reference)
#include <cuda_runtime.h>
#include <math.h>

#define SEQ    1024
#define CDIM   768
#define BATCH  8
#define NHEADS 12
#define HD     64
#define BHN    (BATCH*NHEADS)
#define SCALEF 0.125f

// Scratch: q/k/v in [B, H, N, hd]; ao in [B, N, C].
__device__ float g_q[(size_t)BHN*SEQ*HD];
__device__ float g_k[(size_t)BHN*SEQ*HD];
__device__ float g_v[(size_t)BHN*SEQ*HD];
__device__ float g_ao[(size_t)BATCH*SEQ*CDIM];

__device__ __forceinline__ unsigned f2tf32(float f) {
    unsigned u;
    asm("cvt.rna.tf32.f32 %0, %1;" : "=r"(u) : "f"(f));
    return u;
}

__device__ __forceinline__ void mma_tf32(float c[4], const unsigned a[4],
                                         unsigned b0, unsigned b1) {
    asm volatile(
        "mma.sync.aligned.m16n8k8.row.col.f32.tf32.tf32.f32 "
        "{%0,%1,%2,%3}, {%4,%5,%6,%7}, {%8,%9}, {%0,%1,%2,%3};\n"
        : "+f"(c[0]), "+f"(c[1]), "+f"(c[2]), "+f"(c[3])
        : "r"(a[0]), "r"(a[1]), "r"(a[2]), "r"(a[3]), "r"(b0), "r"(b1));
}

// ---------------------------------------------------------------------------
// Tensor-core GEMM with fragment-permuted SMEM.
// C[M,N] = A[M,K] @ W[N,K]^T + bias[N]; BM=BN=128, BK=32, 8 warps (2x4),
// warp tile 64x32.  A-frag = 1 LDS.128, B-frag = 1 LDS.64.
// A layout: Ap[(mi*4+ks)*128 + (tig*8+g)*4 + hbit*2 + rbit]
// B layout: Bp[(n8*4+ks)*66  + (tig*8+g)*2 + hbit]      (stride 66 de-conflicts STS)
// ---------------------------------------------------------------------------
template<int MODE>
__global__ __launch_bounds__(256)
void gemm_tc(const float* __restrict__ A, const float* __restrict__ W,
             const float* __restrict__ bias, float* __restrict__ Cout,
             int M, int N, int K)
{
    __shared__ unsigned Ap[8 * 4 * 128];   // 4096 words
    __shared__ unsigned Bp[16 * 4 * 66];   // 4224 words

    const int tid  = threadIdx.x;
    const int lane = tid & 31, warp = tid >> 5;
    const int g    = lane >> 2, tig = lane & 3;
    const int wmi  = (warp >> 2) * 4;       // first mi of warp (4 m16 tiles)
    const int wn8  = (warp & 3) * 4;        // first n8 tile of warp
    const int m0   = blockIdx.y * 128;
    const int n0   = blockIdx.x * 128;

    const float* Apt = (MODE == 1) ? (const float*)g_ao : A;
    const float* Ag = Apt + (size_t)m0 * K;
    const float* Wg = W   + (size_t)n0 * K;

    const int lrow = tid >> 1;        // 0..127
    const int lcb  = (tid & 1) * 16;  // 0 / 16

    // writer decomposition
    const int mi4 = (lrow >> 4) * 4;
    const int gA  = lrow & 7;
    const int rA  = (lrow >> 3) & 1;
    const int n84 = (lrow >> 3) * 4;

    // reader lane offsets
    const int lA = (tig * 8 + g) * 4;
    const int lB = (tig * 8 + g) * 2;

    float4 pa[4], pw[4];
    #pragma unroll
    for (int u = 0; u < 4; u++) {
        pa[u] = *(const float4*)(Ag + (size_t)lrow * K + lcb + 4*u);
        pw[u] = *(const float4*)(Wg + (size_t)lrow * K + lcb + 4*u);
    }
    #pragma unroll
    for (int u = 0; u < 4; u++) {
        const int ks = (lcb >> 3) + (u >> 1);
        const int hb = ((lcb >> 2) + u) & 1;
        const float* fa = (const float*)&pa[u];
        const float* fw = (const float*)&pw[u];
        #pragma unroll
        for (int e = 0; e < 4; e++) {
            Ap[(mi4 + ks) * 128 + (e*8 + gA) * 4 + hb*2 + rA] = f2tf32(fa[e]);
            Bp[(n84 + ks) * 66  + (e*8 + gA) * 2 + hb]        = f2tf32(fw[e]);
        }
    }
    __syncthreads();

    float acc[4][4][4];
    #pragma unroll
    for (int mi = 0; mi < 4; mi++)
        #pragma unroll
        for (int nj = 0; nj < 4; nj++)
            #pragma unroll
            for (int c = 0; c < 4; c++) acc[mi][nj][c] = 0.f;

    const int NT = K / 32;
    for (int t = 0; t < NT; t++) {
        if (t + 1 < NT) {
            const int ko = (t + 1) * 32 + lcb;
            #pragma unroll
            for (int u = 0; u < 4; u++) {
                pa[u] = *(const float4*)(Ag + (size_t)lrow * K + ko + 4*u);
                pw[u] = *(const float4*)(Wg + (size_t)lrow * K + ko + 4*u);
            }
        }
        #pragma unroll
        for (int ks = 0; ks < 4; ks++) {
            uint2 bf[4];
            #pragma unroll
            for (int nj = 0; nj < 4; nj++)
                bf[nj] = *(const uint2*)&Bp[((wn8 + nj) * 4 + ks) * 66 + lB];
            #pragma unroll
            for (int mi = 0; mi < 4; mi++) {
                uint4 af4 = *(const uint4*)&Ap[((wmi + mi) * 4 + ks) * 128 + lA];
                unsigned afr[4] = {af4.x, af4.y, af4.z, af4.w};
                #pragma unroll
                for (int nj = 0; nj < 4; nj++)
                    mma_tf32(acc[mi][nj], afr, bf[nj].x, bf[nj].y);
            }
        }
        __syncthreads();
        if (t + 1 < NT) {
            #pragma unroll
            for (int u = 0; u < 4; u++) {
                const int ks = (lcb >> 3) + (u >> 1);
                const int hb = ((lcb >> 2) + u) & 1;
                const float* fa = (const float*)&pa[u];
                const float* fw = (const float*)&pw[u];
                #pragma unroll
                for (int e = 0; e < 4; e++) {
                    Ap[(mi4 + ks) * 128 + (e*8 + gA) * 4 + hb*2 + rA] = f2tf32(fa[e]);
                    Bp[(n84 + ks) * 66  + (e*8 + gA) * 2 + hb]        = f2tf32(fw[e]);
                }
            }
            __syncthreads();
        }
    }

    // epilogue (unchanged layouts)
    float2 bv[4];
    int colv[4];
    #pragma unroll
    for (int nj = 0; nj < 4; nj++) {
        const int col = n0 + (wn8 + nj) * 8 + 2*tig;
        colv[nj] = col;
        bv[nj].x = bias[col];
        bv[nj].y = bias[col + 1];
    }

    if (MODE == 0) {
        const int tsel = n0 / CDIM;
        float* dst = (tsel == 0) ? g_q : (tsel == 1) ? g_k : g_v;
        const int b = m0 >> 10;
        #pragma unroll
        for (int mi = 0; mi < 4; mi++) {
            #pragma unroll
            for (int rr = 0; rr < 2; rr++) {
                const int row = m0 + (wmi + mi) * 16 + g + 8*rr;
                const int n   = row & (SEQ - 1);
                #pragma unroll
                for (int nj = 0; nj < 4; nj++) {
                    const int rem = colv[nj] - tsel * CDIM;
                    const int h = rem >> 6;
                    const int d = rem & 63;
                    float2 v;
                    v.x = acc[mi][nj][2*rr + 0] + bv[nj].x;
                    v.y = acc[mi][nj][2*rr + 1] + bv[nj].y;
                    *(float2*)&dst[(((size_t)b * NHEADS + h) * SEQ + n) * HD + d] = v;
                }
            }
        }
    } else {
        #pragma unroll
        for (int mi = 0; mi < 4; mi++) {
            #pragma unroll
            for (int rr = 0; rr < 2; rr++) {
                const int row = m0 + (wmi + mi) * 16 + g + 8*rr;
                #pragma unroll
                for (int nj = 0; nj < 4; nj++) {
                    float2 v;
                    v.x = acc[mi][nj][2*rr + 0] + bv[nj].x;
                    v.y = acc[mi][nj][2*rr + 1] + bv[nj].y;
                    *(float2*)&Cout[(size_t)row * N + colv[nj]] = v;
                }
            }
        }
    }
}

// ---------------------------------------------------------------------------
// Fused flash attention, fragment-permuted K/V/P SMEM.
// Grid (SEQ/128, B*H), 256 threads = 8 warps; warp w owns rows 16w..16w+15.
// K layout: Ks[(nj*8+ks)*66 + (tig*8+g)*2 + hbit]   (B-operand of QK^T)
// V layout: Vs[(ks*8+nj)*66 + (tig*8+g)*2 + hbit]   (B-operand of PV, k-major slot)
// P layout: Pp[(w*8+ks)*128 + (tig*8+g)*4 + hbit*2 + rbit]  (A-operand, per warp)
// ---------------------------------------------------------------------------
__global__ __launch_bounds__(256)
void attn_tc()
{
    extern __shared__ unsigned sm[];
    unsigned* QPs = sm;                 // phase 1: Q row-major [128][68]; phase 2: Pp
    unsigned* Ks  = sm + 8704;          // 64 tiles * 66
    unsigned* Vs  = sm + 8704 + 4224;   // 64 tiles * 66

    const int tid  = threadIdx.x;
    const int lane = tid & 31, warp = tid >> 5;
    const int g    = lane >> 2, tig = lane & 3;
    const int bh   = blockIdx.y;
    const int qt   = blockIdx.x;

    const int lA = (tig * 8 + g) * 4;
    const int lB = (tig * 8 + g) * 2;

    const float* qg = g_q + (size_t)bh * SEQ * HD + (size_t)qt * 128 * HD;
    const float* kg = g_k + (size_t)bh * SEQ * HD;
    const float* vg = g_v + (size_t)bh * SEQ * HD;

    // load Q 128x64 row-major (tf32)
    {
        const int row = tid >> 1;
        const int cb  = (tid & 1) * 32;
        #pragma unroll
        for (int u = 0; u < 8; u++) {
            float4 f = *(const float4*)(qg + (size_t)row * HD + cb + 4*u);
            QPs[row*68 + cb + 4*u + 0] = f2tf32(f.x);
            QPs[row*68 + cb + 4*u + 1] = f2tf32(f.y);
            QPs[row*68 + cb + 4*u + 2] = f2tf32(f.z);
            QPs[row*68 + cb + 4*u + 3] = f2tf32(f.w);
        }
    }
    __syncthreads();

    // Q fragments register-resident
    unsigned aq[8][4];
    {
        const int r = 16 * warp;
        #pragma unroll
        for (int ks = 0; ks < 8; ks++) {
            aq[ks][0] = QPs[(r + g    ) * 68 + 8*ks + tig];
            aq[ks][1] = QPs[(r + 8 + g) * 68 + 8*ks + tig];
            aq[ks][2] = QPs[(r + g    ) * 68 + 8*ks + tig + 4];
            aq[ks][3] = QPs[(r + 8 + g) * 68 + 8*ks + tig + 4];
        }
    }
    __syncthreads();
    unsigned* Pp = QPs;   // region reused for permuted P

    // per-thread P-write offsets: b=0/1 -> column 2*tig+b within k8 tile
    int poff[2];
    #pragma unroll
    for (int b = 0; b < 2; b++) {
        const int ct = 2*tig + b;
        poff[b] = ((ct & 3) * 8 + g) * 4 + (ct >> 2) * 2;
    }

    float o[8][4];
    #pragma unroll
    for (int nj = 0; nj < 8; nj++)
        #pragma unroll
        for (int c = 0; c < 4; c++) o[nj][c] = 0.f;
    float m0r = -1e30f, m1r = -1e30f, l0 = 0.f, l1 = 0.f;

    // K/V writer decomposition
    const int row = tid >> 2;          // 0..63
    const int cb  = (tid & 3) * 16;
    const int gk  = row & 7;           // K: n within n8 tile
    const int njk = row >> 3;          // K: n8 tile
    const int ksr = row >> 3;          // V: k8 tile (row = k-dim)
    const int cr  = row & 7;
    const int tigr = cr & 3, hbr = cr >> 2;

    for (int kt = 0; kt < SEQ / 64; kt++) {
        {
            const float* kp = kg + (size_t)(kt*64 + row) * HD + cb;
            const float* vp = vg + (size_t)(kt*64 + row) * HD + cb;
            #pragma unroll
            for (int u = 0; u < 4; u++) {
                float4 fk = *(const float4*)(kp + 4*u);
                float4 fv = *(const float4*)(vp + 4*u);
                const int kscol = (cb >> 3) + (u >> 1);
                const int hb    = ((cb >> 2) + u) & 1;
                const float* pk = (const float*)&fk;
                const float* pv = (const float*)&fv;
                #pragma unroll
                for (int e = 0; e < 4; e++) {
                    const int gcol = 4*(u & 1) + e;
                    Ks[(njk*8 + kscol)*66 + (e*8 + gk)*2 + hb]       = f2tf32(pk[e]);
                    Vs[(ksr*8 + kscol)*66 + (tigr*8 + gcol)*2 + hbr] = f2tf32(pv[e]);
                }
            }
        }
        __syncthreads();

        // S = Q @ K^T
        float s[8][4];
        #pragma unroll
        for (int nj = 0; nj < 8; nj++)
            #pragma unroll
            for (int c = 0; c < 4; c++) s[nj][c] = 0.f;

        #pragma unroll
        for (int ks = 0; ks < 8; ks++) {
            #pragma unroll
            for (int nj = 0; nj < 8; nj++) {
                uint2 b = *(const uint2*)&Ks[(nj*8 + ks)*66 + lB];
                mma_tf32(s[nj], aq[ks], b.x, b.y);
            }
        }

        // online softmax
        float rm0 = -1e30f, rm1 = -1e30f;
        #pragma unroll
        for (int nj = 0; nj < 8; nj++) {
            s[nj][0] *= SCALEF; s[nj][1] *= SCALEF;
            s[nj][2] *= SCALEF; s[nj][3] *= SCALEF;
            rm0 = fmaxf(rm0, fmaxf(s[nj][0], s[nj][1]));
            rm1 = fmaxf(rm1, fmaxf(s[nj][2], s[nj][3]));
        }
        rm0 = fmaxf(rm0, __shfl_xor_sync(0xffffffffu, rm0, 1));
        rm0 = fmaxf(rm0, __shfl_xor_sync(0xffffffffu, rm0, 2));
        rm1 = fmaxf(rm1, __shfl_xor_sync(0xffffffffu, rm1, 1));
        rm1 = fmaxf(rm1, __shfl_xor_sync(0xffffffffu, rm1, 2));

        const float mn0 = fmaxf(m0r, rm0);
        const float mn1 = fmaxf(m1r, rm1);
        const float cr0 = __expf(m0r - mn0);
        const float cr1 = __expf(m1r - mn1);
        float rs0 = 0.f, rs1 = 0.f;
        #pragma unroll
        for (int nj = 0; nj < 8; nj++) {
            s[nj][0] = __expf(s[nj][0] - mn0);
            s[nj][1] = __expf(s[nj][1] - mn0);
            s[nj][2] = __expf(s[nj][2] - mn1);
            s[nj][3] = __expf(s[nj][3] - mn1);
            rs0 += s[nj][0] + s[nj][1];
            rs1 += s[nj][2] + s[nj][3];
        }
        rs0 += __shfl_xor_sync(0xffffffffu, rs0, 1);
        rs0 += __shfl_xor_sync(0xffffffffu, rs0, 2);
        rs1 += __shfl_xor_sync(0xffffffffu, rs1, 1);
        rs1 += __shfl_xor_sync(0xffffffffu, rs1, 2);
        l0 = l0 * cr0 + rs0;  m0r = mn0;
        l1 = l1 * cr1 + rs1;  m1r = mn1;
        #pragma unroll
        for (int nj = 0; nj < 8; nj++) {
            o[nj][0] *= cr0; o[nj][1] *= cr0;
            o[nj][2] *= cr1; o[nj][3] *= cr1;
        }

        // stage P directly in A-fragment layout (same warp produces & consumes)
        #pragma unroll
        for (int nj = 0; nj < 8; nj++) {
            unsigned* base = Pp + (warp*8 + nj) * 128;
            base[poff[0] + 0] = f2tf32(s[nj][0]);
            base[poff[1] + 0] = f2tf32(s[nj][1]);
            base[poff[0] + 1] = f2tf32(s[nj][2]);
            base[poff[1] + 1] = f2tf32(s[nj][3]);
        }
        __syncwarp();

        // O += P @ V
        #pragma unroll
        for (int ks = 0; ks < 8; ks++) {
            uint4 pf = *(const uint4*)&Pp[(warp*8 + ks) * 128 + lA];
            unsigned pa[4] = {pf.x, pf.y, pf.z, pf.w};
            #pragma unroll
            for (int nj = 0; nj < 8; nj++) {
                uint2 b = *(const uint2*)&Vs[(ks*8 + nj)*66 + lB];
                mma_tf32(o[nj], pa, b.x, b.y);
            }
        }
        __syncthreads();
    }

    // normalize + write [B, N, C]
    const int b = bh / NHEADS, h = bh % NHEADS;
    const float inv0 = 1.f / l0, inv1 = 1.f / l1;
    const int r0 = qt * 128 + 16*warp + g;
    #pragma unroll
    for (int nj = 0; nj < 8; nj++) {
        const int col = 8*nj + 2*tig;
        float2 v0, v1;
        v0.x = o[nj][0] * inv0; v0.y = o[nj][1] * inv0;
        v1.x = o[nj][2] * inv1; v1.y = o[nj][3] * inv1;
        *(float2*)&g_ao[((size_t)b * SEQ + r0    ) * CDIM + h*HD + col] = v0;
        *(float2*)&g_ao[((size_t)b * SEQ + r0 + 8) * CDIM + h*HD + col] = v1;
    }
}

// ---------------------------------------------------------------------------
// Inputs (metadata order): x, qkv_w, qkv_b, proj_w, proj_b, H, W
// ---------------------------------------------------------------------------
extern "C" void kernel_launch(void* const* d_in, const int* in_sizes, int n_in,
                              void* d_out, int out_size)
{
    (void)in_sizes; (void)n_in; (void)out_size;
    const float* x      = (const float*)d_in[0];
    const float* qkv_w  = (const float*)d_in[1];
    const float* qkv_b  = (const float*)d_in[2];
    const float* proj_w = (const float*)d_in[3];
    const float* proj_b = (const float*)d_in[4];
    float* out = (float*)d_out;

    const int smem_attn = (8704 + 4224 + 4224) * (int)sizeof(unsigned); // 68608 B
    cudaFuncSetAttribute(attn_tc, cudaFuncAttributeMaxDynamicSharedMemorySize, smem_attn);

    // 1) QKV GEMM + bias -> per-head q/k/v
    gemm_tc<0><<<dim3(3 * CDIM / 128, (BATCH * SEQ) / 128), 256>>>(
        x, qkv_w, qkv_b, nullptr, BATCH * SEQ, 3 * CDIM, CDIM);

    // 2) fused flash attention -> g_ao in [B, N, C]
    attn_tc<<<dim3(SEQ / 128, BHN), 256, smem_attn>>>();

    // 3) proj GEMM + bias -> d_out
    gemm_tc<1><<<dim3(CDIM / 128, (BATCH * SEQ) / 128), 256>>>(
        nullptr, proj_w, proj_b, out, BATCH * SEQ, CDIM, CDIM);
}

// round 9
// speedup vs baseline: 2.2468x; 2.2468x over previous
#include <cuda_runtime.h>
#include <math.h>
#include <stdint.h>

#define SEQ    1024
#define CDIM   768
#define BATCH  8
#define NHEADS 12
#define HD     64
#define BHN    (BATCH*NHEADS)
#define SCALEF 0.125f

// Scratch: q/k/v in [B, H, N, hd]; ao in [B, N, C]; pre-rounded tf32 copies.
__device__ float g_q[(size_t)BHN*SEQ*HD];
__device__ float g_k[(size_t)BHN*SEQ*HD];
__device__ float g_v[(size_t)BHN*SEQ*HD];
__device__ float g_ao[(size_t)BATCH*SEQ*CDIM];
__device__ float g_xr[(size_t)BATCH*SEQ*CDIM];
__device__ float g_wqr[(size_t)3*CDIM*CDIM];
__device__ float g_wpr[(size_t)CDIM*CDIM];

__device__ __forceinline__ unsigned f2tf32(float f) {
    unsigned u;
    asm("cvt.rna.tf32.f32 %0, %1;" : "=r"(u) : "f"(f));
    return u;
}

__device__ __forceinline__ uint32_t smem_u32(const void* p) {
    uint32_t a;
    asm("{ .reg .u64 t; cvta.to.shared.u64 t, %1; cvt.u32.u64 %0, t; }"
        : "=r"(a) : "l"(p));
    return a;
}

__device__ __forceinline__ void cp16(uint32_t dst, const void* src) {
    asm volatile("cp.async.cg.shared.global [%0], [%1], 16;"
                 :: "r"(dst), "l"(__cvta_generic_to_global(src)) : "memory");
}
__device__ __forceinline__ void cp_commit() {
    asm volatile("cp.async.commit_group;" ::: "memory");
}
template<int N>
__device__ __forceinline__ void cp_wait() {
    asm volatile("cp.async.wait_group %0;" :: "n"(N) : "memory");
}

__device__ __forceinline__ void mma_tf32(float c[4], const unsigned a[4],
                                         unsigned b0, unsigned b1) {
    asm volatile(
        "mma.sync.aligned.m16n8k8.row.col.f32.tf32.tf32.f32 "
        "{%0,%1,%2,%3}, {%4,%5,%6,%7}, {%8,%9}, {%0,%1,%2,%3};\n"
        : "+f"(c[0]), "+f"(c[1]), "+f"(c[2]), "+f"(c[3])
        : "r"(a[0]), "r"(a[1]), "r"(a[2]), "r"(a[3]), "r"(b0), "r"(b1));
}

// ---------------------------------------------------------------------------
// Pre-round fp32 -> tf32 bit patterns (rna), stored as float.
// which: 0 -> g_xr, 1 -> g_wqr, 2 -> g_wpr
// ---------------------------------------------------------------------------
__global__ void pre_round(const float* __restrict__ src, int which, int n4)
{
    int i = blockIdx.x * blockDim.x + threadIdx.x;
    if (i >= n4) return;
    float* dst = (which == 0) ? g_xr : (which == 1) ? g_wqr : g_wpr;
    float4 f = ((const float4*)src)[i];
    uint4 u;
    u.x = f2tf32(f.x); u.y = f2tf32(f.y); u.z = f2tf32(f.z); u.w = f2tf32(f.w);
    ((uint4*)dst)[i] = u;
}

// ---------------------------------------------------------------------------
// Tensor-core GEMM (mma.sync tf32), cp.async 2-stage pipeline.
// C[M,N] = A[M,K] @ W[N,K]^T + bias[N]; BM=BN=128, BK=32, 8 warps (2x4),
// warp tile 64x32. SMEM per stage: A[128][36] + W[128][36] (tf32 bits).
// MODE 0: A=g_xr, W=g_wqr, scatter tf32-rounded into g_q/g_k/g_v.
// MODE 1: A=g_ao, W=g_wpr, plain fp32 output.
// ---------------------------------------------------------------------------
#define GST_WORDS (2 * 4608)   // per stage: 4608 A + 4608 B... (two stages total)
template<int MODE>
__global__ __launch_bounds__(256, 2)
void gemm_tc(const float* __restrict__ bias, float* __restrict__ Cout,
             int M, int N, int K)
{
    extern __shared__ unsigned gsm[];   // 2 stages * 9216 words
    const uint32_t sb = smem_u32(gsm);

    const int tid  = threadIdx.x;
    const int lane = tid & 31, warp = tid >> 5;
    const int g    = lane >> 2, tig = lane & 3;
    const int wm   = (warp >> 2) * 64;
    const int wn   = (warp & 3) * 32;
    const int m0   = blockIdx.y * 128;
    const int n0   = blockIdx.x * 128;

    const float* Ag = ((MODE == 1) ? (const float*)g_ao : (const float*)g_xr)
                      + (size_t)m0 * K;
    const float* Wg = ((MODE == 1) ? (const float*)g_wpr : (const float*)g_wqr)
                      + (size_t)n0 * K;

    const int NT = K / 32;

    // stage copy: 1024 16B-chunks each for A and B; 4 per thread each
    auto issue = [&](int t, int s) {
        const int kb = t * 32;
        const uint32_t abase = sb + (s * 9216) * 4;
        const uint32_t wbase = abase + 4608 * 4;
        #pragma unroll
        for (int j = 0; j < 4; j++) {
            const int idx = tid + 256 * j;
            const int r = idx >> 3, c = (idx & 7) << 2;
            cp16(abase + (r * 36 + c) * 4, Ag + (size_t)r * K + kb + c);
            cp16(wbase + (r * 36 + c) * 4, Wg + (size_t)r * K + kb + c);
        }
        cp_commit();
    };

    float acc[4][4][4];
    #pragma unroll
    for (int mi = 0; mi < 4; mi++)
        #pragma unroll
        for (int nj = 0; nj < 4; nj++)
            #pragma unroll
            for (int c = 0; c < 4; c++) acc[mi][nj][c] = 0.f;

    issue(0, 0);
    for (int t = 0; t < NT; t++) {
        const int s = t & 1;
        if (t + 1 < NT) issue(t + 1, s ^ 1);
        if (t + 1 < NT) cp_wait<1>(); else cp_wait<0>();
        __syncthreads();

        const unsigned* Asu = gsm + s * 9216;
        const unsigned* Wsu = Asu + 4608;
        #pragma unroll
        for (int ks = 0; ks < 4; ks++) {
            unsigned b0v[4], b1v[4];
            #pragma unroll
            for (int nj = 0; nj < 4; nj++) {
                b0v[nj] = Wsu[(wn + 8*nj + g) * 36 + 8*ks + tig];
                b1v[nj] = Wsu[(wn + 8*nj + g) * 36 + 8*ks + tig + 4];
            }
            #pragma unroll
            for (int mi = 0; mi < 4; mi++) {
                const int r = wm + 16*mi;
                unsigned afr[4];
                afr[0] = Asu[(r + g    ) * 36 + 8*ks + tig];
                afr[1] = Asu[(r + 8 + g) * 36 + 8*ks + tig];
                afr[2] = Asu[(r + g    ) * 36 + 8*ks + tig + 4];
                afr[3] = Asu[(r + 8 + g) * 36 + 8*ks + tig + 4];
                #pragma unroll
                for (int nj = 0; nj < 4; nj++)
                    mma_tf32(acc[mi][nj], afr, b0v[nj], b1v[nj]);
            }
        }
        __syncthreads();
    }

    float2 bv[4];
    int colv[4];
    #pragma unroll
    for (int nj = 0; nj < 4; nj++) {
        const int col = n0 + wn + 8*nj + 2*tig;
        colv[nj] = col;
        bv[nj].x = bias[col];
        bv[nj].y = bias[col + 1];
    }

    if (MODE == 0) {
        const int tsel = n0 / CDIM;
        float* dst = (tsel == 0) ? g_q : (tsel == 1) ? g_k : g_v;
        const int b = m0 >> 10;
        #pragma unroll
        for (int mi = 0; mi < 4; mi++) {
            #pragma unroll
            for (int rr = 0; rr < 2; rr++) {
                const int row = m0 + wm + 16*mi + g + 8*rr;
                const int n   = row & (SEQ - 1);
                #pragma unroll
                for (int nj = 0; nj < 4; nj++) {
                    const int rem = colv[nj] - tsel * CDIM;
                    const int h = rem >> 6;
                    const int d = rem & 63;
                    float2 v;   // pre-round for attention's tf32 consumption
                    v.x = __uint_as_float(f2tf32(acc[mi][nj][2*rr + 0] + bv[nj].x));
                    v.y = __uint_as_float(f2tf32(acc[mi][nj][2*rr + 1] + bv[nj].y));
                    *(float2*)&dst[(((size_t)b * NHEADS + h) * SEQ + n) * HD + d] = v;
                }
            }
        }
    } else {
        #pragma unroll
        for (int mi = 0; mi < 4; mi++) {
            #pragma unroll
            for (int rr = 0; rr < 2; rr++) {
                const int row = m0 + wm + 16*mi + g + 8*rr;
                #pragma unroll
                for (int nj = 0; nj < 4; nj++) {
                    float2 v;
                    v.x = acc[mi][nj][2*rr + 0] + bv[nj].x;
                    v.y = acc[mi][nj][2*rr + 1] + bv[nj].y;
                    *(float2*)&Cout[(size_t)row * N + colv[nj]] = v;
                }
            }
        }
    }
}

// ---------------------------------------------------------------------------
// Fused flash attention (R3 compute, cp.async staged, double-buffered K/V).
// Grid (SEQ/128, B*H), 256 threads = 8 warps; warp w owns rows 16w..16w+15.
// SMEM words: QPs[0,8704) | K0[8704,+4352) V0[+4608) | K1[17664) V1[22016)
// ---------------------------------------------------------------------------
__global__ __launch_bounds__(256)
void attn_tc()
{
    extern __shared__ unsigned sm[];
    unsigned* QPs = sm;
    const uint32_t sb = smem_u32(sm);

    const int tid  = threadIdx.x;
    const int lane = tid & 31, warp = tid >> 5;
    const int g    = lane >> 2, tig = lane & 3;
    const int bh   = blockIdx.y;
    const int qt   = blockIdx.x;

    const float* qg = g_q + (size_t)bh * SEQ * HD + (size_t)qt * 128 * HD;
    const float* kg = g_k + (size_t)bh * SEQ * HD;
    const float* vg = g_v + (size_t)bh * SEQ * HD;

    auto issue_kv = [&](int kt, int s) {
        const float* kp = kg + (size_t)kt * 64 * HD;
        const float* vp = vg + (size_t)kt * 64 * HD;
        const uint32_t kb = sb + (8704 + s * 8960) * 4;
        const uint32_t vb = kb + 4352 * 4;
        #pragma unroll
        for (int j = 0; j < 4; j++) {
            const int idx = tid + 256 * j;
            const int r = idx >> 4, c = (idx & 15) << 2;
            cp16(kb + (r * 68 + c) * 4, kp + (size_t)r * HD + c);
            cp16(vb + (r * 72 + c) * 4, vp + (size_t)r * HD + c);
        }
        cp_commit();
    };

    // Q (pre-rounded tf32 bits): 2048 chunks, 8 per thread
    #pragma unroll
    for (int j = 0; j < 8; j++) {
        const int idx = tid + 256 * j;
        const int r = idx >> 4, c = (idx & 15) << 2;
        cp16(sb + (r * 68 + c) * 4, qg + (size_t)r * HD + c);
    }
    cp_commit();
    issue_kv(0, 0);
    cp_wait<1>();          // Q group done (kv0 may still be in flight)
    __syncthreads();

    unsigned aq[8][4];
    {
        const int r = 16 * warp;
        #pragma unroll
        for (int ks = 0; ks < 8; ks++) {
            aq[ks][0] = QPs[(r + g    ) * 68 + 8*ks + tig];
            aq[ks][1] = QPs[(r + 8 + g) * 68 + 8*ks + tig];
            aq[ks][2] = QPs[(r + g    ) * 68 + 8*ks + tig + 4];
            aq[ks][3] = QPs[(r + 8 + g) * 68 + 8*ks + tig + 4];
        }
    }
    __syncthreads();

    float o[8][4];
    #pragma unroll
    for (int nj = 0; nj < 8; nj++)
        #pragma unroll
        for (int c = 0; c < 4; c++) o[nj][c] = 0.f;
    float m0r = -1e30f, m1r = -1e30f, l0 = 0.f, l1 = 0.f;

    for (int kt = 0; kt < SEQ / 64; kt++) {
        const int s = kt & 1;
        if (kt + 1 < SEQ / 64) issue_kv(kt + 1, s ^ 1);
        if (kt + 1 < SEQ / 64) cp_wait<1>(); else cp_wait<0>();
        __syncthreads();

        const unsigned* Ks = sm + 8704 + s * 8960;
        const unsigned* Vs = Ks + 4352;

        float sc[8][4];
        #pragma unroll
        for (int nj = 0; nj < 8; nj++)
            #pragma unroll
            for (int c = 0; c < 4; c++) sc[nj][c] = 0.f;

        #pragma unroll
        for (int ks = 0; ks < 8; ks++) {
            #pragma unroll
            for (int nj = 0; nj < 8; nj++) {
                const unsigned b0 = Ks[(8*nj + g) * 68 + 8*ks + tig];
                const unsigned b1 = Ks[(8*nj + g) * 68 + 8*ks + tig + 4];
                mma_tf32(sc[nj], aq[ks], b0, b1);
            }
        }

        float rm0 = -1e30f, rm1 = -1e30f;
        #pragma unroll
        for (int nj = 0; nj < 8; nj++) {
            sc[nj][0] *= SCALEF; sc[nj][1] *= SCALEF;
            sc[nj][2] *= SCALEF; sc[nj][3] *= SCALEF;
            rm0 = fmaxf(rm0, fmaxf(sc[nj][0], sc[nj][1]));
            rm1 = fmaxf(rm1, fmaxf(sc[nj][2], sc[nj][3]));
        }
        rm0 = fmaxf(rm0, __shfl_xor_sync(0xffffffffu, rm0, 1));
        rm0 = fmaxf(rm0, __shfl_xor_sync(0xffffffffu, rm0, 2));
        rm1 = fmaxf(rm1, __shfl_xor_sync(0xffffffffu, rm1, 1));
        rm1 = fmaxf(rm1, __shfl_xor_sync(0xffffffffu, rm1, 2));

        const float mn0 = fmaxf(m0r, rm0);
        const float mn1 = fmaxf(m1r, rm1);
        const float cr0 = __expf(m0r - mn0);
        const float cr1 = __expf(m1r - mn1);
        float rs0 = 0.f, rs1 = 0.f;
        #pragma unroll
        for (int nj = 0; nj < 8; nj++) {
            sc[nj][0] = __expf(sc[nj][0] - mn0);
            sc[nj][1] = __expf(sc[nj][1] - mn0);
            sc[nj][2] = __expf(sc[nj][2] - mn1);
            sc[nj][3] = __expf(sc[nj][3] - mn1);
            rs0 += sc[nj][0] + sc[nj][1];
            rs1 += sc[nj][2] + sc[nj][3];
        }
        rs0 += __shfl_xor_sync(0xffffffffu, rs0, 1);
        rs0 += __shfl_xor_sync(0xffffffffu, rs0, 2);
        rs1 += __shfl_xor_sync(0xffffffffu, rs1, 1);
        rs1 += __shfl_xor_sync(0xffffffffu, rs1, 2);
        l0 = l0 * cr0 + rs0;  m0r = mn0;
        l1 = l1 * cr1 + rs1;  m1r = mn1;
        #pragma unroll
        for (int nj = 0; nj < 8; nj++) {
            o[nj][0] *= cr0; o[nj][1] *= cr0;
            o[nj][2] *= cr1; o[nj][3] *= cr1;
        }

        {
            const int r0 = 16*warp + g;
            #pragma unroll
            for (int nj = 0; nj < 8; nj++) {
                QPs[ r0      * 68 + 8*nj + 2*tig    ] = f2tf32(sc[nj][0]);
                QPs[ r0      * 68 + 8*nj + 2*tig + 1] = f2tf32(sc[nj][1]);
                QPs[(r0 + 8) * 68 + 8*nj + 2*tig    ] = f2tf32(sc[nj][2]);
                QPs[(r0 + 8) * 68 + 8*nj + 2*tig + 1] = f2tf32(sc[nj][3]);
            }
        }
        __syncwarp();

        #pragma unroll
        for (int ks = 0; ks < 8; ks++) {
            unsigned pa[4];
            pa[0] = QPs[(16*warp + g    ) * 68 + 8*ks + tig];
            pa[1] = QPs[(16*warp + 8 + g) * 68 + 8*ks + tig];
            pa[2] = QPs[(16*warp + g    ) * 68 + 8*ks + tig + 4];
            pa[3] = QPs[(16*warp + 8 + g) * 68 + 8*ks + tig + 4];
            #pragma unroll
            for (int nj = 0; nj < 8; nj++) {
                const unsigned b0 = Vs[(8*ks + tig    ) * 72 + 8*nj + g];
                const unsigned b1 = Vs[(8*ks + tig + 4) * 72 + 8*nj + g];
                mma_tf32(o[nj], pa, b0, b1);
            }
        }
        __syncthreads();
    }

    // normalize + write [B, N, C], pre-rounded for the proj GEMM
    const int b = bh / NHEADS, h = bh % NHEADS;
    const float inv0 = 1.f / l0, inv1 = 1.f / l1;
    const int r0 = qt * 128 + 16*warp + g;
    #pragma unroll
    for (int nj = 0; nj < 8; nj++) {
        const int col = 8*nj + 2*tig;
        float2 v0, v1;
        v0.x = __uint_as_float(f2tf32(o[nj][0] * inv0));
        v0.y = __uint_as_float(f2tf32(o[nj][1] * inv0));
        v1.x = __uint_as_float(f2tf32(o[nj][2] * inv1));
        v1.y = __uint_as_float(f2tf32(o[nj][3] * inv1));
        *(float2*)&g_ao[((size_t)b * SEQ + r0    ) * CDIM + h*HD + col] = v0;
        *(float2*)&g_ao[((size_t)b * SEQ + r0 + 8) * CDIM + h*HD + col] = v1;
    }
}

// ---------------------------------------------------------------------------
// Inputs (metadata order): x, qkv_w, qkv_b, proj_w, proj_b, H, W
// ---------------------------------------------------------------------------
extern "C" void kernel_launch(void* const* d_in, const int* in_sizes, int n_in,
                              void* d_out, int out_size)
{
    (void)in_sizes; (void)n_in; (void)out_size;
    const float* x      = (const float*)d_in[0];
    const float* qkv_w  = (const float*)d_in[1];
    const float* qkv_b  = (const float*)d_in[2];
    const float* proj_w = (const float*)d_in[3];
    const float* proj_b = (const float*)d_in[4];
    float* out = (float*)d_out;

    const int smem_gemm = 2 * 9216 * (int)sizeof(unsigned);   // 73728 B
    const int smem_attn = (8704 + 2 * 8960) * (int)sizeof(unsigned); // 106496 B
    cudaFuncSetAttribute(gemm_tc<0>, cudaFuncAttributeMaxDynamicSharedMemorySize, smem_gemm);
    cudaFuncSetAttribute(gemm_tc<1>, cudaFuncAttributeMaxDynamicSharedMemorySize, smem_gemm);
    cudaFuncSetAttribute(attn_tc,    cudaFuncAttributeMaxDynamicSharedMemorySize, smem_attn);

    // 0) pre-round inputs to tf32 bit patterns
    pre_round<<<(BATCH*SEQ*CDIM/4 + 255)/256, 256>>>(x, 0, BATCH*SEQ*CDIM/4);
    pre_round<<<(3*CDIM*CDIM/4   + 255)/256, 256>>>(qkv_w, 1, 3*CDIM*CDIM/4);
    pre_round<<<(CDIM*CDIM/4     + 255)/256, 256>>>(proj_w, 2, CDIM*CDIM/4);

    // 1) QKV GEMM + bias -> per-head q/k/v (tf32-rounded)
    gemm_tc<0><<<dim3(3 * CDIM / 128, (BATCH * SEQ) / 128), 256, smem_gemm>>>(
        qkv_b, nullptr, BATCH * SEQ, 3 * CDIM, CDIM);

    // 2) fused flash attention -> g_ao (tf32-rounded) in [B, N, C]
    attn_tc<<<dim3(SEQ / 128, BHN), 256, smem_attn>>>();

    // 3) proj GEMM + bias -> d_out (fp32)
    gemm_tc<1><<<dim3(CDIM / 128, (BATCH * SEQ) / 128), 256, smem_gemm>>>(
        proj_b, out, BATCH * SEQ, CDIM, CDIM);
}

// round 10
// speedup vs baseline: 2.2922x; 1.0202x over previous
#include <cuda_runtime.h>
#include <math.h>
#include <stdint.h>

#define SEQ    1024
#define CDIM   768
#define BATCH  8
#define NHEADS 12
#define HD     64
#define BHN    (BATCH*NHEADS)
#define SCALEF 0.125f

// Scratch. q/k in [B,H,N,hd] with hd-permuted storage; v natural; ao k-permuted.
__device__ float g_q[(size_t)BHN*SEQ*HD];
__device__ float g_k[(size_t)BHN*SEQ*HD];
__device__ float g_v[(size_t)BHN*SEQ*HD];
__device__ float g_ao[(size_t)BATCH*SEQ*CDIM];
__device__ float g_xr[(size_t)BATCH*SEQ*CDIM];     // x, tf32, col k-perm
__device__ float g_wqr[(size_t)3*CDIM*CDIM];       // qkv_w, tf32, col k-perm, q/k rows perm
__device__ float g_wpr[(size_t)CDIM*CDIM];         // proj_w, tf32, col k-perm
__device__ float g_bqkv[3*CDIM];                   // qkv_b, q/k sections row-perm

__device__ __forceinline__ unsigned f2tf32(float f) {
    unsigned u;
    asm("cvt.rna.tf32.f32 %0, %1;" : "=r"(u) : "f"(f));
    return u;
}
__device__ __forceinline__ uint32_t smem_u32(const void* p) {
    uint32_t a;
    asm("{ .reg .u64 t; cvta.to.shared.u64 t, %1; cvt.u32.u64 %0, t; }"
        : "=r"(a) : "l"(p));
    return a;
}
__device__ __forceinline__ void cp16(uint32_t dst, const void* src) {
    asm volatile("cp.async.cg.shared.global [%0], [%1], 16;"
                 :: "r"(dst), "l"(__cvta_generic_to_global(src)) : "memory");
}
__device__ __forceinline__ void cp_commit() {
    asm volatile("cp.async.commit_group;" ::: "memory");
}
template<int N>
__device__ __forceinline__ void cp_wait() {
    asm volatile("cp.async.wait_group %0;" :: "n"(N) : "memory");
}
__device__ __forceinline__ void mma_tf32(float c[4], const unsigned a[4],
                                         unsigned b0, unsigned b1) {
    asm volatile(
        "mma.sync.aligned.m16n8k8.row.col.f32.tf32.tf32.f32 "
        "{%0,%1,%2,%3}, {%4,%5,%6,%7}, {%8,%9}, {%0,%1,%2,%3};\n"
        : "+f"(c[0]), "+f"(c[1]), "+f"(c[2]), "+f"(c[3])
        : "r"(a[0]), "r"(a[1]), "r"(a[2]), "r"(a[3]), "r"(b0), "r"(b1));
}
// storage position j within an 8-group holds logical element invp(j)
__device__ __forceinline__ int invp(int j) { return ((j & 1) << 2) | (j >> 1); }

// ---------------------------------------------------------------------------
// Pre-round + permute. Column groups of 8: stored = [o0,o4,o1,o5,o2,o6,o3,o7].
// which: 0 -> g_xr (no row perm), 1 -> g_wqr (rows<1536 perm), 2 -> g_wpr.
// One thread per 8-col group.
// ---------------------------------------------------------------------------
__global__ void pre_perm(const float* __restrict__ src, int which, int ngroups, int K)
{
    int i = blockIdx.x * blockDim.x + threadIdx.x;
    if (i >= ngroups) return;
    const int gpr = K >> 3;                  // groups per row
    const int row = i / gpr, cg = i - row * gpr;
    int srow = row;
    if (which == 1 && row < 2 * CDIM) srow = (row & ~7) | invp(row & 7);
    const float* s = src + (size_t)srow * K + cg * 8;
    float4 f0 = *(const float4*)(s);
    float4 f1 = *(const float4*)(s + 4);
    float* dst = (which == 0) ? g_xr : (which == 1) ? g_wqr : g_wpr;
    uint4 u0, u1;
    u0.x = f2tf32(f0.x); u0.y = f2tf32(f1.x); u0.z = f2tf32(f0.y); u0.w = f2tf32(f1.y);
    u1.x = f2tf32(f0.z); u1.y = f2tf32(f1.z); u1.z = f2tf32(f0.w); u1.w = f2tf32(f1.w);
    uint4* d = (uint4*)(dst + (size_t)row * K + cg * 8);
    d[0] = u0; d[1] = u1;
}

__global__ void perm_bias(const float* __restrict__ qkv_b)
{
    int j = blockIdx.x * blockDim.x + threadIdx.x;
    if (j >= 3 * CDIM) return;
    int sj = (j < 2 * CDIM) ? ((j & ~7) | invp(j & 7)) : j;
    g_bqkv[j] = qkv_b[sj];
}

// ---------------------------------------------------------------------------
// Tensor-core GEMM (mma.sync tf32), cp.async 2-stage, LDS.64 fragments.
// BM=BN=128, BK=32, 8 warps (2x4), warp tile 64x32. Row stride 40 words.
// MODE 0: A=g_xr, W=g_wqr, bias=g_bqkv, scatter tf32-rounded q/k/v.
// MODE 1: A=g_ao, W=g_wpr, plain fp32 output.
// ---------------------------------------------------------------------------
template<int MODE>
__global__ __launch_bounds__(256, 2)
void gemm_tc(const float* __restrict__ biasp, float* __restrict__ Cout,
             int M, int N, int K)
{
    extern __shared__ unsigned gsm[];   // 2 stages * (5120 A + 5120 B)
    const uint32_t sb = smem_u32(gsm);

    const int tid  = threadIdx.x;
    const int lane = tid & 31, warp = tid >> 5;
    const int g    = lane >> 2, tig = lane & 3;
    const int wm   = (warp >> 2) * 64;
    const int wn   = (warp & 3) * 32;
    const int m0   = blockIdx.y * 128;
    const int n0   = blockIdx.x * 128;

    const float* Ag = ((MODE == 1) ? (const float*)g_ao : (const float*)g_xr)
                      + (size_t)m0 * K;
    const float* Wg = ((MODE == 1) ? (const float*)g_wpr : (const float*)g_wqr)
                      + (size_t)n0 * K;
    const float* bias = (MODE == 0) ? (const float*)g_bqkv : biasp;

    const int NT = K / 32;

    auto issue = [&](int t, int s) {
        const int kb = t * 32;
        const uint32_t abase = sb + (s * 10240) * 4;
        const uint32_t wbase = abase + 5120 * 4;
        #pragma unroll
        for (int j = 0; j < 4; j++) {
            const int idx = tid + 256 * j;
            const int r = idx >> 3, c = (idx & 7) << 2;
            cp16(abase + (r * 40 + c) * 4, Ag + (size_t)r * K + kb + c);
            cp16(wbase + (r * 40 + c) * 4, Wg + (size_t)r * K + kb + c);
        }
        cp_commit();
    };

    float acc[4][4][4];
    #pragma unroll
    for (int mi = 0; mi < 4; mi++)
        #pragma unroll
        for (int nj = 0; nj < 4; nj++)
            #pragma unroll
            for (int c = 0; c < 4; c++) acc[mi][nj][c] = 0.f;

    issue(0, 0);
    for (int t = 0; t < NT; t++) {
        const int s = t & 1;
        if (t + 1 < NT) issue(t + 1, s ^ 1);
        if (t + 1 < NT) cp_wait<1>(); else cp_wait<0>();
        __syncthreads();

        const unsigned* Asu = gsm + s * 10240;
        const unsigned* Wsu = Asu + 5120;
        #pragma unroll
        for (int ks = 0; ks < 4; ks++) {
            const int kc = 8 * ks + 2 * tig;
            uint2 bfr[4];
            #pragma unroll
            for (int nj = 0; nj < 4; nj++)
                bfr[nj] = *(const uint2*)&Wsu[(wn + 8*nj + g) * 40 + kc];
            #pragma unroll
            for (int mi = 0; mi < 4; mi++) {
                uint2 a01 = *(const uint2*)&Asu[(wm + 16*mi + g    ) * 40 + kc];
                uint2 a23 = *(const uint2*)&Asu[(wm + 16*mi + 8 + g) * 40 + kc];
                unsigned afr[4] = {a01.x, a23.x, a01.y, a23.y};
                #pragma unroll
                for (int nj = 0; nj < 4; nj++)
                    mma_tf32(acc[mi][nj], afr, bfr[nj].x, bfr[nj].y);
            }
        }
        __syncthreads();
    }

    float2 bv[4];
    int colv[4];
    #pragma unroll
    for (int nj = 0; nj < 4; nj++) {
        const int col = n0 + wn + 8*nj + 2*tig;
        colv[nj] = col;
        bv[nj].x = bias[col];
        bv[nj].y = bias[col + 1];
    }

    if (MODE == 0) {
        const int tsel = n0 / CDIM;
        float* dst = (tsel == 0) ? g_q : (tsel == 1) ? g_k : g_v;
        const int b = m0 >> 10;
        #pragma unroll
        for (int mi = 0; mi < 4; mi++) {
            #pragma unroll
            for (int rr = 0; rr < 2; rr++) {
                const int row = m0 + wm + 16*mi + g + 8*rr;
                const int n   = row & (SEQ - 1);
                #pragma unroll
                for (int nj = 0; nj < 4; nj++) {
                    const int rem = colv[nj] - tsel * CDIM;
                    const int h = rem >> 6;
                    const int d = rem & 63;
                    float2 v;
                    v.x = __uint_as_float(f2tf32(acc[mi][nj][2*rr + 0] + bv[nj].x));
                    v.y = __uint_as_float(f2tf32(acc[mi][nj][2*rr + 1] + bv[nj].y));
                    *(float2*)&dst[(((size_t)b * NHEADS + h) * SEQ + n) * HD + d] = v;
                }
            }
        }
    } else {
        #pragma unroll
        for (int mi = 0; mi < 4; mi++) {
            #pragma unroll
            for (int rr = 0; rr < 2; rr++) {
                const int row = m0 + wm + 16*mi + g + 8*rr;
                #pragma unroll
                for (int nj = 0; nj < 4; nj++) {
                    float2 v;
                    v.x = acc[mi][nj][2*rr + 0] + bv[nj].x;
                    v.y = acc[mi][nj][2*rr + 1] + bv[nj].y;
                    *(float2*)&Cout[(size_t)row * N + colv[nj]] = v;
                }
            }
        }
    }
}

// ---------------------------------------------------------------------------
// Fused flash attention. Strides 72 (bank-clean LDS.64). Q/K/P frag = LDS.64.
// SMEM words: QP[0,9216) | stage s at 9216+s*9216: K(4608) then V(4608).
// ---------------------------------------------------------------------------
__global__ __launch_bounds__(256)
void attn_tc()
{
    extern __shared__ unsigned sm[];
    unsigned* QPs = sm;
    const uint32_t sb = smem_u32(sm);

    const int tid  = threadIdx.x;
    const int lane = tid & 31, warp = tid >> 5;
    const int g    = lane >> 2, tig = lane & 3;
    const int bh   = blockIdx.y;
    const int qt   = blockIdx.x;

    // P permuted-store positions: logical cols (2tig, 2tig+1) -> (p0, p0+2)
    const int p0 = ((tig & 1) ? 4 : 0) + (tig >> 1);

    const float* qg = g_q + (size_t)bh * SEQ * HD + (size_t)qt * 128 * HD;
    const float* kg = g_k + (size_t)bh * SEQ * HD;
    const float* vg = g_v + (size_t)bh * SEQ * HD;

    auto issue_kv = [&](int kt, int s) {
        const float* kp = kg + (size_t)kt * 64 * HD;
        const float* vp = vg + (size_t)kt * 64 * HD;
        const uint32_t kb = sb + (9216 + s * 9216) * 4;
        const uint32_t vb = kb + 4608 * 4;
        #pragma unroll
        for (int j = 0; j < 4; j++) {
            const int idx = tid + 256 * j;
            const int r = idx >> 4, c = (idx & 15) << 2;
            cp16(kb + (r * 72 + c) * 4, kp + (size_t)r * HD + c);
            cp16(vb + (r * 72 + c) * 4, vp + (size_t)r * HD + c);
        }
        cp_commit();
    };

    #pragma unroll
    for (int j = 0; j < 8; j++) {
        const int idx = tid + 256 * j;
        const int r = idx >> 4, c = (idx & 15) << 2;
        cp16(sb + (r * 72 + c) * 4, qg + (size_t)r * HD + c);
    }
    cp_commit();
    issue_kv(0, 0);
    cp_wait<1>();
    __syncthreads();

    unsigned aq[8][4];
    {
        const int r = 16 * warp;
        #pragma unroll
        for (int ks = 0; ks < 8; ks++) {
            const int kc = 8*ks + 2*tig;
            uint2 q01 = *(const uint2*)&QPs[(r + g    ) * 72 + kc];
            uint2 q23 = *(const uint2*)&QPs[(r + 8 + g) * 72 + kc];
            aq[ks][0] = q01.x; aq[ks][1] = q23.x; aq[ks][2] = q01.y; aq[ks][3] = q23.y;
        }
    }
    __syncthreads();

    float o[8][4];
    #pragma unroll
    for (int nj = 0; nj < 8; nj++)
        #pragma unroll
        for (int c = 0; c < 4; c++) o[nj][c] = 0.f;
    float m0r = -1e30f, m1r = -1e30f, l0 = 0.f, l1 = 0.f;

    for (int kt = 0; kt < SEQ / 64; kt++) {
        const int s = kt & 1;
        if (kt + 1 < SEQ / 64) issue_kv(kt + 1, s ^ 1);
        if (kt + 1 < SEQ / 64) cp_wait<1>(); else cp_wait<0>();
        __syncthreads();

        const unsigned* Ks = sm + 9216 + s * 9216;
        const unsigned* Vs = Ks + 4608;

        float sc[8][4];
        #pragma unroll
        for (int nj = 0; nj < 8; nj++)
            #pragma unroll
            for (int c = 0; c < 4; c++) sc[nj][c] = 0.f;

        #pragma unroll
        for (int ks = 0; ks < 8; ks++) {
            const int kc = 8*ks + 2*tig;
            #pragma unroll
            for (int nj = 0; nj < 8; nj++) {
                uint2 b = *(const uint2*)&Ks[(8*nj + g) * 72 + kc];
                mma_tf32(sc[nj], aq[ks], b.x, b.y);
            }
        }

        float rm0 = -1e30f, rm1 = -1e30f;
        #pragma unroll
        for (int nj = 0; nj < 8; nj++) {
            sc[nj][0] *= SCALEF; sc[nj][1] *= SCALEF;
            sc[nj][2] *= SCALEF; sc[nj][3] *= SCALEF;
            rm0 = fmaxf(rm0, fmaxf(sc[nj][0], sc[nj][1]));
            rm1 = fmaxf(rm1, fmaxf(sc[nj][2], sc[nj][3]));
        }
        rm0 = fmaxf(rm0, __shfl_xor_sync(0xffffffffu, rm0, 1));
        rm0 = fmaxf(rm0, __shfl_xor_sync(0xffffffffu, rm0, 2));
        rm1 = fmaxf(rm1, __shfl_xor_sync(0xffffffffu, rm1, 1));
        rm1 = fmaxf(rm1, __shfl_xor_sync(0xffffffffu, rm1, 2));

        const float mn0 = fmaxf(m0r, rm0);
        const float mn1 = fmaxf(m1r, rm1);
        const float cr0 = __expf(m0r - mn0);
        const float cr1 = __expf(m1r - mn1);
        float rs0 = 0.f, rs1 = 0.f;
        #pragma unroll
        for (int nj = 0; nj < 8; nj++) {
            sc[nj][0] = __expf(sc[nj][0] - mn0);
            sc[nj][1] = __expf(sc[nj][1] - mn0);
            sc[nj][2] = __expf(sc[nj][2] - mn1);
            sc[nj][3] = __expf(sc[nj][3] - mn1);
            rs0 += sc[nj][0] + sc[nj][1];
            rs1 += sc[nj][2] + sc[nj][3];
        }
        rs0 += __shfl_xor_sync(0xffffffffu, rs0, 1);
        rs0 += __shfl_xor_sync(0xffffffffu, rs0, 2);
        rs1 += __shfl_xor_sync(0xffffffffu, rs1, 1);
        rs1 += __shfl_xor_sync(0xffffffffu, rs1, 2);
        l0 = l0 * cr0 + rs0;  m0r = mn0;
        l1 = l1 * cr1 + rs1;  m1r = mn1;
        #pragma unroll
        for (int nj = 0; nj < 8; nj++) {
            o[nj][0] *= cr0; o[nj][1] *= cr0;
            o[nj][2] *= cr1; o[nj][3] *= cr1;
        }

        // stage P at permuted n-positions (so P-frag loads are LDS.64)
        {
            const int r0 = 16*warp + g;
            #pragma unroll
            for (int nj = 0; nj < 8; nj++) {
                QPs[ r0      * 72 + 8*nj + p0    ] = f2tf32(sc[nj][0]);
                QPs[ r0      * 72 + 8*nj + p0 + 2] = f2tf32(sc[nj][1]);
                QPs[(r0 + 8) * 72 + 8*nj + p0    ] = f2tf32(sc[nj][2]);
                QPs[(r0 + 8) * 72 + 8*nj + p0 + 2] = f2tf32(sc[nj][3]);
            }
        }
        __syncwarp();

        #pragma unroll
        for (int ks = 0; ks < 8; ks++) {
            const int kc = 8*ks + 2*tig;
            uint2 p01 = *(const uint2*)&QPs[(16*warp + g    ) * 72 + kc];
            uint2 p23 = *(const uint2*)&QPs[(16*warp + 8 + g) * 72 + kc];
            unsigned pa[4] = {p01.x, p23.x, p01.y, p23.y};
            #pragma unroll
            for (int nj = 0; nj < 8; nj++) {
                const unsigned b0 = Vs[(8*ks + tig    ) * 72 + 8*nj + g];
                const unsigned b1 = Vs[(8*ks + tig + 4) * 72 + 8*nj + g];
                mma_tf32(o[nj], pa, b0, b1);
            }
        }
        __syncthreads();
    }

    // normalize + write g_ao at k-permuted positions (tf32-rounded, for proj)
    const int b = bh / NHEADS, h = bh % NHEADS;
    const float inv0 = 1.f / l0, inv1 = 1.f / l1;
    const int r0 = qt * 128 + 16*warp + g;
    float* ao0 = g_ao + ((size_t)b * SEQ + r0    ) * CDIM + h * HD;
    float* ao1 = g_ao + ((size_t)b * SEQ + r0 + 8) * CDIM + h * HD;
    #pragma unroll
    for (int nj = 0; nj < 8; nj++) {
        const int q0 = 8*nj + p0, q1 = 8*nj + p0 + 2;
        ao0[q0] = __uint_as_float(f2tf32(o[nj][0] * inv0));
        ao0[q1] = __uint_as_float(f2tf32(o[nj][1] * inv0));
        ao1[q0] = __uint_as_float(f2tf32(o[nj][2] * inv1));
        ao1[q1] = __uint_as_float(f2tf32(o[nj][3] * inv1));
    }
}

// ---------------------------------------------------------------------------
// Inputs (metadata order): x, qkv_w, qkv_b, proj_w, proj_b, H, W
// ---------------------------------------------------------------------------
extern "C" void kernel_launch(void* const* d_in, const int* in_sizes, int n_in,
                              void* d_out, int out_size)
{
    (void)in_sizes; (void)n_in; (void)out_size;
    const float* x      = (const float*)d_in[0];
    const float* qkv_w  = (const float*)d_in[1];
    const float* qkv_b  = (const float*)d_in[2];
    const float* proj_w = (const float*)d_in[3];
    const float* proj_b = (const float*)d_in[4];
    float* out = (float*)d_out;

    const int smem_gemm = 2 * 10240 * (int)sizeof(unsigned);   // 81920 B
    const int smem_attn = (9216 + 2 * 9216) * (int)sizeof(unsigned); // 110592 B
    cudaFuncSetAttribute(gemm_tc<0>, cudaFuncAttributeMaxDynamicSharedMemorySize, smem_gemm);
    cudaFuncSetAttribute(gemm_tc<1>, cudaFuncAttributeMaxDynamicSharedMemorySize, smem_gemm);
    cudaFuncSetAttribute(attn_tc,    cudaFuncAttributeMaxDynamicSharedMemorySize, smem_attn);

    // 0) pre-round + permute operands
    {
        const int gx = BATCH*SEQ*CDIM/8, gw = 3*CDIM*CDIM/8, gp = CDIM*CDIM/8;
        pre_perm<<<(gx + 255)/256, 256>>>(x, 0, gx, CDIM);
        pre_perm<<<(gw + 255)/256, 256>>>(qkv_w, 1, gw, CDIM);
        pre_perm<<<(gp + 255)/256, 256>>>(proj_w, 2, gp, CDIM);
        perm_bias<<<(3*CDIM + 255)/256, 256>>>(qkv_b);
    }

    // 1) QKV GEMM + bias -> per-head q/k/v (q/k d-permuted via W-row perm)
    gemm_tc<0><<<dim3(3 * CDIM / 128, (BATCH * SEQ) / 128), 256, smem_gemm>>>(
        nullptr, nullptr, BATCH * SEQ, 3 * CDIM, CDIM);

    // 2) fused flash attention -> g_ao (k-permuted, tf32-rounded)
    attn_tc<<<dim3(SEQ / 128, BHN), 256, smem_attn>>>();

    // 3) proj GEMM + bias -> d_out (fp32, natural layout)
    gemm_tc<1><<<dim3(CDIM / 128, (BATCH * SEQ) / 128), 256, smem_gemm>>>(
        proj_b, out, BATCH * SEQ, CDIM, CDIM);
}